// round 1
// baseline (speedup 1.0000x reference)
#include <cuda_runtime.h>
#include <math.h>

// Problem constants
#define NE 32     // experts
#define NC 64     // capacity (rows per expert)
#define ND 1024   // d_model
#define NF 4096   // d_ff

// Intermediate h = gelu(x@W1+b1): [E, C, F] fp32 = 32 MB scratch (device global,
// no allocation -> allowed by harness rules).
__device__ float g_h[(size_t)NE * NC * NF];

// Tiling: BM x BN output tile per block, BK k-slab, 256 threads, 4x8 per thread.
#define BM 64
#define BN 128
#define BK 16
#define TM 4
#define TN 8
#define NTHREADS 256

__device__ __forceinline__ float gelu_tanh(float v) {
    // jax.nn.gelu default (approximate=True):
    // 0.5*x*(1+tanh(sqrt(2/pi)*(x+0.044715*x^3)))
    const float c0 = 0.7978845608028654f;
    const float c1 = 0.044715f;
    float u = c0 * fmaf(c1 * v * v, v, v);
    return 0.5f * v * (1.0f + tanhf(u));
}

// C[E, NC, N] = act( A[E, NC, K] @ B[E, K, N] + bias[E, N] )
template <bool GELU>
__global__ __launch_bounds__(NTHREADS, 2)
void ffn_gemm_kernel(const float* __restrict__ A_all,
                     const float* __restrict__ B_all,
                     const float* __restrict__ bias_all,
                     float* __restrict__ C_all,
                     int K, int N)
{
    const int e    = blockIdx.y;
    const int nblk = blockIdx.x * BN;

    const float* __restrict__ A  = A_all    + (size_t)e * NC * K;
    const float* __restrict__ B  = B_all    + (size_t)e * K  * N;
    const float* __restrict__ bb = bias_all + (size_t)e * N + nblk;
    float* __restrict__       Co = C_all    + (size_t)e * NC * N;

    __shared__ float As[BM][BK + 1];   // +1 pad: conflict-free column reads
    __shared__ float Bs[BK][BN];

    const int tid = threadIdx.x;
    const int tn  = tid & 15;          // 16 groups along N
    const int tm  = tid >> 4;          // 16 groups along M
    const int m0  = tm * TM;
    const int n0  = tn * TN;

    // A tile load map: one float4 per thread (64 rows x 4 kvecs)
    const int a_row = tid >> 2;
    const int a_k4  = (tid & 3) * 4;
    // B tile load map: two float4 per thread, fully coalesced rows
    const int b_row = tid >> 5;
    const int b_c4  = (tid & 31) * 4;

    float acc[TM][TN];
    #pragma unroll
    for (int i = 0; i < TM; i++)
        #pragma unroll
        for (int j = 0; j < TN; j++) acc[i][j] = 0.0f;

    for (int k0 = 0; k0 < K; k0 += BK) {
        // --- stage A (64 x 16) ---
        float4 av = *reinterpret_cast<const float4*>(A + (size_t)a_row * K + k0 + a_k4);
        As[a_row][a_k4 + 0] = av.x;
        As[a_row][a_k4 + 1] = av.y;
        As[a_row][a_k4 + 2] = av.z;
        As[a_row][a_k4 + 3] = av.w;

        // --- stage B (16 x 128) ---
        #pragma unroll
        for (int rr = 0; rr < 2; rr++) {
            int r = b_row + rr * 8;
            *reinterpret_cast<float4*>(&Bs[r][b_c4]) =
                *reinterpret_cast<const float4*>(B + (size_t)(k0 + r) * N + nblk + b_c4);
        }
        __syncthreads();

        // --- FMA block: 32 FFMA per k-step per thread ---
        #pragma unroll
        for (int kk = 0; kk < BK; kk++) {
            float a[TM], b[TN];
            #pragma unroll
            for (int i = 0; i < TM; i++) a[i] = As[m0 + i][kk];
            #pragma unroll
            for (int j = 0; j < TN; j += 4) {
                float4 bv = *reinterpret_cast<const float4*>(&Bs[kk][n0 + j]);
                b[j + 0] = bv.x; b[j + 1] = bv.y; b[j + 2] = bv.z; b[j + 3] = bv.w;
            }
            #pragma unroll
            for (int i = 0; i < TM; i++)
                #pragma unroll
                for (int j = 0; j < TN; j++)
                    acc[i][j] = fmaf(a[i], b[j], acc[i][j]);
        }
        __syncthreads();
    }

    // --- epilogue: bias (+ gelu) + vectorized store ---
    float bv[TN];
    #pragma unroll
    for (int j = 0; j < TN; j++) bv[j] = bb[n0 + j];

    #pragma unroll
    for (int i = 0; i < TM; i++) {
        float o[TN];
        #pragma unroll
        for (int j = 0; j < TN; j++) {
            float v = acc[i][j] + bv[j];
            o[j] = GELU ? gelu_tanh(v) : v;
        }
        float* dst = Co + (size_t)(m0 + i) * N + nblk + n0;
        #pragma unroll
        for (int j = 0; j < TN; j += 4) {
            float4 w4 = make_float4(o[j], o[j + 1], o[j + 2], o[j + 3]);
            *reinterpret_cast<float4*>(dst + j) = w4;
        }
    }
}

extern "C" void kernel_launch(void* const* d_in, const int* in_sizes, int n_in,
                              void* d_out, int out_size)
{
    (void)in_sizes; (void)n_in; (void)out_size;
    const float* x  = (const float*)d_in[0];   // [1, E*C, D]
    const float* W1 = (const float*)d_in[1];   // [E, D, F]
    const float* b1 = (const float*)d_in[2];   // [E, F]
    const float* W2 = (const float*)d_in[3];   // [E, F, D]
    const float* b2 = (const float*)d_in[4];   // [E, D]
    float* out = (float*)d_out;                // [1, E*C, D]

    float* hbuf = nullptr;
    cudaGetSymbolAddress((void**)&hbuf, g_h);  // query only, graph-capture safe

    // GEMM1: [E,64,1024] @ [E,1024,4096] -> gelu -> g_h
    dim3 g1(NF / BN, NE);
    ffn_gemm_kernel<true><<<g1, NTHREADS>>>(x, W1, b1, hbuf, ND, NF);

    // GEMM2: [E,64,4096] @ [E,4096,1024] -> out
    dim3 g2(ND / BN, NE);
    ffn_gemm_kernel<false><<<g2, NTHREADS>>>(hbuf, W2, b2, out, NF, ND);
}

// round 3
// speedup vs baseline: 3.0066x; 3.0066x over previous
#include <cuda_runtime.h>
#include <cstdint>

#define NE 32     // experts
#define NC 64     // rows per expert
#define ND 1024   // d_model
#define NF 4096   // d_ff

// 32 MB intermediate (static device global -> no allocation)
__device__ float g_h[(size_t)NE * NC * NF];

// smem tile geometry (floats)
#define ROWF   36                 // padded row stride (32 data + 4 pad) -> conflict-free
#define ASZ    (64  * ROWF)       // A tile: 64 rows
#define BSZ    (128 * ROWF)       // B tile: 128 rows (n-major)
#define STAGEF (ASZ + BSZ)        // one pipeline stage

__device__ __forceinline__ uint32_t to_tf32u(float x) {
    uint32_t y; asm("cvt.rna.tf32.f32 %0, %1;" : "=r"(y) : "f"(x)); return y;
}
__device__ __forceinline__ float tanh_fast(float x) {
    float y; asm("tanh.approx.f32 %0, %1;" : "=f"(y) : "f"(x)); return y;
}
__device__ __forceinline__ float gelu_tanh(float v) {
    const float c0 = 0.7978845608028654f;
    const float c1 = 0.044715f;
    float u = c0 * fmaf(c1 * v * v, v, v);
    return 0.5f * v * (1.0f + tanh_fast(u));
}

// m16n8k4 tf32 MMA (plain sm_80+ PTX, no arch-'a' features)
__device__ __forceinline__ void mma4(float (&c)[4], uint32_t a0, uint32_t a1, uint32_t b0) {
    asm volatile("mma.sync.aligned.m16n8k4.row.col.f32.tf32.tf32.f32 "
                 "{%0,%1,%2,%3}, {%4,%5}, {%6}, {%0,%1,%2,%3};"
                 : "+f"(c[0]), "+f"(c[1]), "+f"(c[2]), "+f"(c[3])
                 : "r"(a0), "r"(a1), "r"(b0));
}

// C[e, 0:64, n0:n0+128] = act( A[e,0:64,0:K] @ B[e,0:K,n0:n0+128] + bias )
// smem k-permutation within each 32-k slab: k = 4j + t  stored at  pos = t*8 + j
template <bool GELU, int K, int N>
__global__ __launch_bounds__(256, 2)
void moe_tf32(const float* __restrict__ A_all, const float* __restrict__ B_all,
              const float* __restrict__ bias_all, float* __restrict__ C_all)
{
    constexpr int NS = K / 32;
    extern __shared__ float sm[];

    const int tid  = threadIdx.x;
    const int lane = tid & 31;
    const int wid  = tid >> 5;
    const int e    = blockIdx.y;
    const int n0   = blockIdx.x * 128;

    const float* Ae = A_all    + (size_t)e * NC * K;
    const float* Bg = B_all    + (size_t)e * K * N + n0;
    const float* be = bias_all + (size_t)e * N + n0;
    float*       Ce = C_all    + (size_t)e * NC * N + n0;

    // producer mapping
    const int ar = tid >> 2, aq = tid & 3;        // A: row, float4-quad
    const int bh = wid >> 2, bt = wid & 3;        // B: k-half, k-phase

    // consumer mapping
    const int wm = wid & 1, wn = wid >> 1;        // warp grid 2(M) x 4(N)
    const int g  = lane >> 2, tg = lane & 3;

    float acc[2][4][4];                            // [matom][natom][c0..c3]
    #pragma unroll
    for (int i = 0; i < 2; i++)
        #pragma unroll
        for (int j = 0; j < 4; j++)
            #pragma unroll
            for (int k = 0; k < 4; k++) acc[i][j][k] = 0.0f;

    // staging registers for gmem->smem
    uint32_t sa[2][4];                             // A: two float4 (k-phase major)
    uint32_t sb[4][4];                             // B: [n-block][j]

    // ---- gmem -> regs ----
    auto LDGS = [&](int k0) {
        const float* ap = Ae + (size_t)ar * K + k0;
        #pragma unroll
        for (int f2 = 0; f2 < 2; f2++) {
            float4 v = *reinterpret_cast<const float4*>(ap + 4 * (aq + 4 * f2));
            sa[f2][0] = to_tf32u(v.x); sa[f2][1] = to_tf32u(v.y);
            sa[f2][2] = to_tf32u(v.z); sa[f2][3] = to_tf32u(v.w);
        }
        #pragma unroll
        for (int nb = 0; nb < 4; nb++) {
            int n = nb * 32 + lane;
            #pragma unroll
            for (int j = 0; j < 4; j++)
                sb[nb][j] = to_tf32u(Bg[(size_t)(k0 + 16 * bh + 4 * j + bt) * N + n]);
        }
    };

    // ---- regs -> smem (k-permuted) ----
    auto STS = [&](int buf) {
        uint32_t* sAi = reinterpret_cast<uint32_t*>(sm + buf * STAGEF);
        uint32_t* sBi = sAi + ASZ;
        #pragma unroll
        for (int f2 = 0; f2 < 2; f2++) {
            int f = aq + 4 * f2;                   // j index
            #pragma unroll
            for (int t = 0; t < 4; t++)            // k = 4f + t -> pos t*8 + f
                sAi[ar * ROWF + t * 8 + f] = sa[f2][t];
        }
        #pragma unroll
        for (int nb = 0; nb < 4; nb++) {
            int n = nb * 32 + lane;                // k = 16h+4j+t -> pos t*8+4h+j
            *reinterpret_cast<uint4*>(&sBi[n * ROWF + bt * 8 + 4 * bh]) =
                make_uint4(sb[nb][0], sb[nb][1], sb[nb][2], sb[nb][3]);
        }
    };

    // ---- smem -> frags -> MMA ----
    auto COMPUTE = [&](int buf) {
        const uint32_t* sAi = reinterpret_cast<const uint32_t*>(sm + buf * STAGEF);
        const uint32_t* sBi = sAi + ASZ;
        #pragma unroll
        for (int h = 0; h < 2; h++) {
            uint4 a[2][2];                         // [matom][row-half]
            #pragma unroll
            for (int ma = 0; ma < 2; ma++)
                #pragma unroll
                for (int rh = 0; rh < 2; rh++)
                    a[ma][rh] = *reinterpret_cast<const uint4*>(
                        &sAi[(wm * 32 + ma * 16 + rh * 8 + g) * ROWF + tg * 8 + h * 4]);
            uint4 b[4];
            #pragma unroll
            for (int na = 0; na < 4; na++)
                b[na] = *reinterpret_cast<const uint4*>(
                    &sBi[(wn * 32 + na * 8 + g) * ROWF + tg * 8 + h * 4]);
            #pragma unroll
            for (int j = 0; j < 4; j++) {
                #pragma unroll
                for (int ma = 0; ma < 2; ma++) {
                    uint32_t a0 = reinterpret_cast<const uint32_t*>(&a[ma][0])[j];
                    uint32_t a1 = reinterpret_cast<const uint32_t*>(&a[ma][1])[j];
                    #pragma unroll
                    for (int na = 0; na < 4; na++)
                        mma4(acc[ma][na], a0, a1,
                             reinterpret_cast<const uint32_t*>(&b[na])[j]);
                }
            }
        }
    };

    // ---- pipeline ----
    LDGS(0);
    STS(0);
    __syncthreads();
    for (int s = 0; s < NS; s++) {
        if (s + 1 < NS) LDGS((s + 1) * 32);
        COMPUTE(s & 1);
        if (s + 1 < NS) STS((s + 1) & 1);
        __syncthreads();
    }

    // ---- epilogue: bias (+gelu) + store ----
    float2 bvv[4];
    #pragma unroll
    for (int na = 0; na < 4; na++)
        bvv[na] = *reinterpret_cast<const float2*>(be + wn * 32 + na * 8 + 2 * tg);

    #pragma unroll
    for (int ma = 0; ma < 2; ma++) {
        int row0 = wm * 32 + ma * 16 + g;
        #pragma unroll
        for (int na = 0; na < 4; na++) {
            int col = wn * 32 + na * 8 + 2 * tg;
            float v0 = acc[ma][na][0] + bvv[na].x;
            float v1 = acc[ma][na][1] + bvv[na].y;
            float v2 = acc[ma][na][2] + bvv[na].x;
            float v3 = acc[ma][na][3] + bvv[na].y;
            if (GELU) { v0 = gelu_tanh(v0); v1 = gelu_tanh(v1);
                        v2 = gelu_tanh(v2); v3 = gelu_tanh(v3); }
            *reinterpret_cast<float2*>(Ce + (size_t)row0 * N + col)       = make_float2(v0, v1);
            *reinterpret_cast<float2*>(Ce + (size_t)(row0 + 8) * N + col) = make_float2(v2, v3);
        }
    }
}

// ---------------- host launch ----------------
extern "C" void kernel_launch(void* const* d_in, const int* in_sizes, int n_in,
                              void* d_out, int out_size)
{
    (void)in_sizes; (void)n_in; (void)out_size;
    const float* x  = (const float*)d_in[0];   // [1, E*C, D]
    const float* W1 = (const float*)d_in[1];   // [E, D, F]
    const float* b1 = (const float*)d_in[2];   // [E, F]
    const float* W2 = (const float*)d_in[3];   // [E, F, D]
    const float* b2 = (const float*)d_in[4];   // [E, D]
    float* out = (float*)d_out;                // [1, E*C, D]

    float* hbuf = nullptr;
    cudaGetSymbolAddress((void**)&hbuf, g_h);

    const int smem = 2 * STAGEF * (int)sizeof(float);   // 55296 B

    cudaFuncSetAttribute((const void*)moe_tf32<true,  ND, NF>,
                         cudaFuncAttributeMaxDynamicSharedMemorySize, smem);
    cudaFuncSetAttribute((const void*)moe_tf32<false, NF, ND>,
                         cudaFuncAttributeMaxDynamicSharedMemorySize, smem);

    // GEMM1: h = gelu(x @ W1 + b1)   [E,64,1024] x [E,1024,4096]
    moe_tf32<true,  ND, NF><<<dim3(NF / 128, NE), 256, smem>>>(x, W1, b1, hbuf);
    // GEMM2: out = h @ W2 + b2       [E,64,4096] x [E,4096,1024]
    moe_tf32<false, NF, ND><<<dim3(ND / 128, NE), 256, smem>>>(hbuf, W2, b2, out);
}

// round 4
// speedup vs baseline: 3.3641x; 1.1189x over previous
#include <cuda_runtime.h>
#include <cstdint>

#define NE 32     // experts
#define NC 64     // rows per expert
#define ND 1024   // d_model
#define NF 4096   // d_ff

// 32 MB intermediate (static device global -> no allocation)
__device__ float g_h[(size_t)NE * NC * NF];

// smem tile geometry (floats)
#define ROWF   36                 // padded row stride (32 data + 4 pad) -> conflict-free
#define ASZ    (64  * ROWF)       // A tile: 64 rows
#define BSZ    (128 * ROWF)       // B tile: 128 rows (n-major)
#define STAGEF (ASZ + BSZ)        // one pipeline stage

__device__ __forceinline__ uint32_t to_tf32u(float x) {
    uint32_t y; asm("cvt.rna.tf32.f32 %0, %1;" : "=r"(y) : "f"(x)); return y;
}
__device__ __forceinline__ float tanh_fast(float x) {
    float y; asm("tanh.approx.f32 %0, %1;" : "=f"(y) : "f"(x)); return y;
}
__device__ __forceinline__ float gelu_tanh(float v) {
    const float c0 = 0.7978845608028654f;
    const float c1 = 0.044715f;
    float u = c0 * fmaf(c1 * v * v, v, v);
    return 0.5f * v * (1.0f + tanh_fast(u));
}

// m16n8k8 tf32 MMA (full-rate HMMA.1688 atom, plain sm_80+ PTX)
__device__ __forceinline__ void mma8(float (&c)[4],
                                     uint32_t a0, uint32_t a1, uint32_t a2, uint32_t a3,
                                     uint32_t b0, uint32_t b1) {
    asm volatile("mma.sync.aligned.m16n8k8.row.col.f32.tf32.tf32.f32 "
                 "{%0,%1,%2,%3}, {%4,%5,%6,%7}, {%8,%9}, {%0,%1,%2,%3};"
                 : "+f"(c[0]), "+f"(c[1]), "+f"(c[2]), "+f"(c[3])
                 : "r"(a0), "r"(a1), "r"(a2), "r"(a3), "r"(b0), "r"(b1));
}

// C[e, 0:64, n0:n0+128] = act( A[e,0:64,0:K] @ B[e,0:K,n0:n0+128] + bias )
// smem k-permutation within each 32-k slab: k = 4j + t  stored at  pos = t*8 + j
// => a thread's uint4 at pos tg*8+4h holds k = 16h + 4q + tg (q=0..3); pairs
// (q,q+1) are exactly the (k, k+4) halves an m16n8k8 fragment consumes.
template <bool GELU, int K, int N>
__global__ __launch_bounds__(256, 2)
void moe_tf32(const float* __restrict__ A_all, const float* __restrict__ B_all,
              const float* __restrict__ bias_all, float* __restrict__ C_all)
{
    constexpr int NS = K / 32;
    extern __shared__ float sm[];

    const int tid  = threadIdx.x;
    const int lane = tid & 31;
    const int wid  = tid >> 5;
    const int e    = blockIdx.y;
    const int n0   = blockIdx.x * 128;

    const float* Ae = A_all    + (size_t)e * NC * K;
    const float* Bg = B_all    + (size_t)e * K * N + n0;
    const float* be = bias_all + (size_t)e * N + n0;
    float*       Ce = C_all    + (size_t)e * NC * N + n0;

    // producer mapping
    const int ar = tid >> 2, aq = tid & 3;        // A: row, float4-quad
    const int bh = wid >> 2, bt = wid & 3;        // B: k-half, k-phase

    // consumer mapping
    const int wm = wid & 1, wn = wid >> 1;        // warp grid 2(M) x 4(N)
    const int g  = lane >> 2, tg = lane & 3;

    float acc[2][4][4];                            // [matom][natom][c0..c3]
    #pragma unroll
    for (int i = 0; i < 2; i++)
        #pragma unroll
        for (int j = 0; j < 4; j++)
            #pragma unroll
            for (int k = 0; k < 4; k++) acc[i][j][k] = 0.0f;

    // staging registers for gmem->smem
    uint32_t sa[2][4];                             // A: two float4 (k-phase major)
    uint32_t sb[4][4];                             // B: [n-block][j]

    // ---- gmem -> regs ----
    auto LDGS = [&](int k0) {
        const float* ap = Ae + (size_t)ar * K + k0;
        #pragma unroll
        for (int f2 = 0; f2 < 2; f2++) {
            float4 v = *reinterpret_cast<const float4*>(ap + 4 * (aq + 4 * f2));
            sa[f2][0] = to_tf32u(v.x); sa[f2][1] = to_tf32u(v.y);
            sa[f2][2] = to_tf32u(v.z); sa[f2][3] = to_tf32u(v.w);
        }
        #pragma unroll
        for (int nb = 0; nb < 4; nb++) {
            int n = nb * 32 + lane;
            #pragma unroll
            for (int j = 0; j < 4; j++)
                sb[nb][j] = to_tf32u(Bg[(size_t)(k0 + 16 * bh + 4 * j + bt) * N + n]);
        }
    };

    // ---- regs -> smem (k-permuted) ----
    auto STS = [&](int buf) {
        uint32_t* sAi = reinterpret_cast<uint32_t*>(sm + buf * STAGEF);
        uint32_t* sBi = sAi + ASZ;
        #pragma unroll
        for (int f2 = 0; f2 < 2; f2++) {
            int f = aq + 4 * f2;                   // j index
            #pragma unroll
            for (int t = 0; t < 4; t++)            // k = 4f + t -> pos t*8 + f
                sAi[ar * ROWF + t * 8 + f] = sa[f2][t];
        }
        #pragma unroll
        for (int nb = 0; nb < 4; nb++) {
            int n = nb * 32 + lane;                // k = 16h+4j+t -> pos t*8+4h+j
            *reinterpret_cast<uint4*>(&sBi[n * ROWF + bt * 8 + 4 * bh]) =
                make_uint4(sb[nb][0], sb[nb][1], sb[nb][2], sb[nb][3]);
        }
    };

    // ---- smem -> frags -> MMA (m16n8k8) ----
    auto COMPUTE = [&](int buf) {
        const uint32_t* sAi = reinterpret_cast<const uint32_t*>(sm + buf * STAGEF);
        const uint32_t* sBi = sAi + ASZ;
        #pragma unroll
        for (int h = 0; h < 2; h++) {
            uint4 a[2][2];                         // [matom][row-half]
            #pragma unroll
            for (int ma = 0; ma < 2; ma++)
                #pragma unroll
                for (int rh = 0; rh < 2; rh++)
                    a[ma][rh] = *reinterpret_cast<const uint4*>(
                        &sAi[(wm * 32 + ma * 16 + rh * 8 + g) * ROWF + tg * 8 + h * 4]);
            uint4 b[4];
            #pragma unroll
            for (int na = 0; na < 4; na++)
                b[na] = *reinterpret_cast<const uint4*>(
                    &sBi[(wn * 32 + na * 8 + g) * ROWF + tg * 8 + h * 4]);
            // two k8 steps per h: register pairs (0,1) and (2,3)
            #pragma unroll
            for (int s2 = 0; s2 < 2; s2++) {
                #pragma unroll
                for (int ma = 0; ma < 2; ma++) {
                    uint32_t a0 = reinterpret_cast<const uint32_t*>(&a[ma][0])[2 * s2 + 0];
                    uint32_t a1 = reinterpret_cast<const uint32_t*>(&a[ma][1])[2 * s2 + 0];
                    uint32_t a2 = reinterpret_cast<const uint32_t*>(&a[ma][0])[2 * s2 + 1];
                    uint32_t a3 = reinterpret_cast<const uint32_t*>(&a[ma][1])[2 * s2 + 1];
                    #pragma unroll
                    for (int na = 0; na < 4; na++) {
                        uint32_t b0 = reinterpret_cast<const uint32_t*>(&b[na])[2 * s2 + 0];
                        uint32_t b1 = reinterpret_cast<const uint32_t*>(&b[na])[2 * s2 + 1];
                        mma8(acc[ma][na], a0, a1, a2, a3, b0, b1);
                    }
                }
            }
        }
    };

    // ---- pipeline ----
    LDGS(0);
    STS(0);
    __syncthreads();
    for (int s = 0; s < NS; s++) {
        if (s + 1 < NS) LDGS((s + 1) * 32);
        COMPUTE(s & 1);
        if (s + 1 < NS) STS((s + 1) & 1);
        __syncthreads();
    }

    // ---- epilogue: bias (+gelu) + store ----
    float2 bvv[4];
    #pragma unroll
    for (int na = 0; na < 4; na++)
        bvv[na] = *reinterpret_cast<const float2*>(be + wn * 32 + na * 8 + 2 * tg);

    #pragma unroll
    for (int ma = 0; ma < 2; ma++) {
        int row0 = wm * 32 + ma * 16 + g;
        #pragma unroll
        for (int na = 0; na < 4; na++) {
            int col = wn * 32 + na * 8 + 2 * tg;
            float v0 = acc[ma][na][0] + bvv[na].x;
            float v1 = acc[ma][na][1] + bvv[na].y;
            float v2 = acc[ma][na][2] + bvv[na].x;
            float v3 = acc[ma][na][3] + bvv[na].y;
            if (GELU) { v0 = gelu_tanh(v0); v1 = gelu_tanh(v1);
                        v2 = gelu_tanh(v2); v3 = gelu_tanh(v3); }
            *reinterpret_cast<float2*>(Ce + (size_t)row0 * N + col)       = make_float2(v0, v1);
            *reinterpret_cast<float2*>(Ce + (size_t)(row0 + 8) * N + col) = make_float2(v2, v3);
        }
    }
}

// ---------------- host launch ----------------
extern "C" void kernel_launch(void* const* d_in, const int* in_sizes, int n_in,
                              void* d_out, int out_size)
{
    (void)in_sizes; (void)n_in; (void)out_size;
    const float* x  = (const float*)d_in[0];   // [1, E*C, D]
    const float* W1 = (const float*)d_in[1];   // [E, D, F]
    const float* b1 = (const float*)d_in[2];   // [E, F]
    const float* W2 = (const float*)d_in[3];   // [E, F, D]
    const float* b2 = (const float*)d_in[4];   // [E, D]
    float* out = (float*)d_out;                // [1, E*C, D]

    float* hbuf = nullptr;
    cudaGetSymbolAddress((void**)&hbuf, g_h);

    const int smem = 2 * STAGEF * (int)sizeof(float);   // 55296 B

    cudaFuncSetAttribute((const void*)moe_tf32<true,  ND, NF>,
                         cudaFuncAttributeMaxDynamicSharedMemorySize, smem);
    cudaFuncSetAttribute((const void*)moe_tf32<false, NF, ND>,
                         cudaFuncAttributeMaxDynamicSharedMemorySize, smem);

    // GEMM1: h = gelu(x @ W1 + b1)   [E,64,1024] x [E,1024,4096]
    moe_tf32<true,  ND, NF><<<dim3(NF / 128, NE), 256, smem>>>(x, W1, b1, hbuf);
    // GEMM2: out = h @ W2 + b2       [E,64,4096] x [E,4096,1024]
    moe_tf32<false, NF, ND><<<dim3(ND / 128, NE), 256, smem>>>(hbuf, W2, b2, out);
}

// round 5
// speedup vs baseline: 4.8978x; 1.4559x over previous
#include <cuda_runtime.h>
#include <cstdint>

#define NE 32     // experts
#define NC 64     // rows per expert
#define ND 1024   // d_model
#define NF 4096   // d_ff

// 32 MB intermediate (static device global -> no allocation)
__device__ float g_h[(size_t)NE * NC * NF];

// ---- smem geometry (words) ----
#define AST 36                    // A row stride: 32 k + 4 pad  -> LDS banks = lane id
#define BST 136                   // B row stride: 128 n + 8 pad -> LDS banks 8(l%4)+l/4
#define A_STAGE_W (64 * AST)      // 2304 words
#define B_STAGE_W (32 * BST)      // 4352 words
#define STAGE_W   (A_STAGE_W + B_STAGE_W)   // 6656 words = 26624 B
#define NSTAGE 3

__device__ __forceinline__ uint32_t smem_u32(const void* p) {
    uint32_t a;
    asm("{ .reg .u64 t; cvta.to.shared.u64 t, %1; cvt.u32.u64 %0, t; }" : "=r"(a) : "l"(p));
    return a;
}
__device__ __forceinline__ uint32_t to_tf32u(float x) {
    uint32_t y; asm("cvt.rna.tf32.f32 %0, %1;" : "=r"(y) : "f"(x)); return y;
}
__device__ __forceinline__ float tanh_fast(float x) {
    float y; asm("tanh.approx.f32 %0, %1;" : "=f"(y) : "f"(x)); return y;
}
__device__ __forceinline__ float gelu_tanh(float v) {
    const float c0 = 0.7978845608028654f;
    const float c1 = 0.044715f;
    float u = c0 * fmaf(c1 * v * v, v, v);
    return 0.5f * v * (1.0f + tanh_fast(u));
}
__device__ __forceinline__ void cp16(uint32_t dst, const void* src) {
    asm volatile("cp.async.cg.shared.global [%0], [%1], 16;" :: "r"(dst), "l"(src));
}
#define CP_COMMIT() asm volatile("cp.async.commit_group;" ::: "memory")
#define CP_WAIT1()  asm volatile("cp.async.wait_group 1;"  ::: "memory")

// m16n8k8 tf32 MMA (full-rate atom, plain sm_80+ PTX)
__device__ __forceinline__ void mma8(float (&c)[4],
                                     uint32_t a0, uint32_t a1, uint32_t a2, uint32_t a3,
                                     uint32_t b0, uint32_t b1) {
    asm volatile("mma.sync.aligned.m16n8k8.row.col.f32.tf32.tf32.f32 "
                 "{%0,%1,%2,%3}, {%4,%5,%6,%7}, {%8,%9}, {%0,%1,%2,%3};"
                 : "+f"(c[0]), "+f"(c[1]), "+f"(c[2]), "+f"(c[3])
                 : "r"(a0), "r"(a1), "r"(a2), "r"(a3), "r"(b0), "r"(b1));
}

// C[e, 0:64, n0:n0+128] = act( A[e,0:64,0:K] @ B[e,0:K,n0:n0+128] + bias )
template <bool GELU, int K, int N>
__global__ __launch_bounds__(256, 2)
void moe_tf32(const float* __restrict__ A_all, const float* __restrict__ B_all,
              const float* __restrict__ bias_all, float* __restrict__ C_all)
{
    constexpr int NS = K / 32;
    extern __shared__ float sm[];
    const uint32_t smb = smem_u32(sm);

    const int tid  = threadIdx.x;
    const int lane = tid & 31;
    const int wid  = tid >> 5;
    const int e    = blockIdx.y;
    const int n0   = blockIdx.x * 128;

    const float* Ae = A_all    + (size_t)e * NC * K;
    const float* Bg = B_all    + (size_t)e * K * N + n0;
    const float* be = bias_all + (size_t)e * N + n0;
    float*       Ce = C_all    + (size_t)e * NC * N + n0;

    const int wm = wid & 1, wn = wid >> 1;     // warp grid 2(M) x 4(N)
    const int g  = lane >> 2, tg = lane & 3;

    float acc[2][4][4];
    #pragma unroll
    for (int i = 0; i < 2; i++)
        #pragma unroll
        for (int j = 0; j < 4; j++)
            #pragma unroll
            for (int k = 0; k < 4; k++) acc[i][j][k] = 0.0f;

    // ---- async stage fill: A[64x32] (row-major), B[32x128] (k-major rows) ----
    auto ISSUE = [&](int s) {
        const int buf = s % NSTAGE;
        const uint32_t sA = smb + (uint32_t)(buf * STAGE_W) * 4u;
        const uint32_t sB = sA + A_STAGE_W * 4u;
        const int k0 = s * 32;
        #pragma unroll
        for (int r = 0; r < 2; r++) {              // A: 512 x 16B
            int idx = r * 256 + tid;
            int row = idx >> 3, c = idx & 7;
            cp16(sA + (uint32_t)(row * AST + c * 4) * 4u,
                 Ae + (size_t)row * K + k0 + c * 4);
        }
        #pragma unroll
        for (int r = 0; r < 4; r++) {              // B: 1024 x 16B
            int idx = r * 256 + tid;
            int row = idx >> 5, c = idx & 31;
            cp16(sB + (uint32_t)(row * BST + c * 4) * 4u,
                 Bg + (size_t)(k0 + row) * N + c * 4);
        }
    };

    // ---- consume one stage: scattered conflict-free LDS.32 + cvt + MMA ----
    auto COMPUTE = [&](int buf) {
        const float* sAf = sm + buf * STAGE_W;
        const float* sBf = sAf + A_STAGE_W;
        #pragma unroll
        for (int h = 0; h < 4; h++) {              // four k8 steps
            uint32_t A0[2], A1[2], A2[2], A3[2];
            #pragma unroll
            for (int ma = 0; ma < 2; ma++) {
                const float* p = sAf + (wm * 32 + ma * 16 + g) * AST + h * 8 + tg;
                A0[ma] = to_tf32u(p[0]);
                A2[ma] = to_tf32u(p[4]);
                A1[ma] = to_tf32u(p[8 * AST]);
                A3[ma] = to_tf32u(p[8 * AST + 4]);
            }
            #pragma unroll
            for (int na = 0; na < 4; na++) {
                const float* q = sBf + (h * 8 + tg) * BST + wn * 32 + na * 8 + g;
                uint32_t B0 = to_tf32u(q[0]);
                uint32_t B1 = to_tf32u(q[4 * BST]);
                mma8(acc[0][na], A0[0], A1[0], A2[0], A3[0], B0, B1);
                mma8(acc[1][na], A0[1], A1[1], A2[1], A3[1], B0, B1);
            }
        }
    };

    // ---- 3-stage pipeline ----
    ISSUE(0); CP_COMMIT();
    ISSUE(1); CP_COMMIT();
    CP_WAIT1();                    // stage 0 resident
    __syncthreads();
    for (int s = 0; s < NS; s++) {
        if (s + 2 < NS) ISSUE(s + 2);
        CP_COMMIT();               // commit every iter (possibly empty group)
        COMPUTE(s % NSTAGE);
        CP_WAIT1();                // next stage resident (<=1 group in flight)
        __syncthreads();
    }

    // ---- epilogue: bias (+gelu) + store ----
    float2 bvv[4];
    #pragma unroll
    for (int na = 0; na < 4; na++)
        bvv[na] = *reinterpret_cast<const float2*>(be + wn * 32 + na * 8 + 2 * tg);

    #pragma unroll
    for (int ma = 0; ma < 2; ma++) {
        int row0 = wm * 32 + ma * 16 + g;
        #pragma unroll
        for (int na = 0; na < 4; na++) {
            int col = wn * 32 + na * 8 + 2 * tg;
            float v0 = acc[ma][na][0] + bvv[na].x;
            float v1 = acc[ma][na][1] + bvv[na].y;
            float v2 = acc[ma][na][2] + bvv[na].x;
            float v3 = acc[ma][na][3] + bvv[na].y;
            if (GELU) { v0 = gelu_tanh(v0); v1 = gelu_tanh(v1);
                        v2 = gelu_tanh(v2); v3 = gelu_tanh(v3); }
            *reinterpret_cast<float2*>(Ce + (size_t)row0 * N + col)       = make_float2(v0, v1);
            *reinterpret_cast<float2*>(Ce + (size_t)(row0 + 8) * N + col) = make_float2(v2, v3);
        }
    }
}

// ---------------- host launch ----------------
extern "C" void kernel_launch(void* const* d_in, const int* in_sizes, int n_in,
                              void* d_out, int out_size)
{
    (void)in_sizes; (void)n_in; (void)out_size;
    const float* x  = (const float*)d_in[0];   // [1, E*C, D]
    const float* W1 = (const float*)d_in[1];   // [E, D, F]
    const float* b1 = (const float*)d_in[2];   // [E, F]
    const float* W2 = (const float*)d_in[3];   // [E, F, D]
    const float* b2 = (const float*)d_in[4];   // [E, D]
    float* out = (float*)d_out;                // [1, E*C, D]

    float* hbuf = nullptr;
    cudaGetSymbolAddress((void**)&hbuf, g_h);

    const int smem = NSTAGE * STAGE_W * (int)sizeof(float);   // 79872 B

    cudaFuncSetAttribute((const void*)moe_tf32<true,  ND, NF>,
                         cudaFuncAttributeMaxDynamicSharedMemorySize, smem);
    cudaFuncSetAttribute((const void*)moe_tf32<false, NF, ND>,
                         cudaFuncAttributeMaxDynamicSharedMemorySize, smem);

    // GEMM1: h = gelu(x @ W1 + b1)   [E,64,1024] x [E,1024,4096]
    moe_tf32<true,  ND, NF><<<dim3(NF / 128, NE), 256, smem>>>(x, W1, b1, hbuf);
    // GEMM2: out = h @ W2 + b2       [E,64,4096] x [E,4096,1024]
    moe_tf32<false, NF, ND><<<dim3(ND / 128, NE), 256, smem>>>(hbuf, W2, b2, out);
}

// round 6
// speedup vs baseline: 5.0437x; 1.0298x over previous
#include <cuda_runtime.h>
#include <cstdint>

#define NE 32     // experts
#define NC 64     // rows per expert
#define ND 1024   // d_model
#define NF 4096   // d_ff
#define KSPLIT2 2048              // GEMM2 K-split length

// static scratch (no allocation): h (32MB), rounded x (8MB), GEMM2 partials (16MB)
__device__ float g_h[(size_t)NE * NC * NF];
__device__ float g_x[(size_t)NE * NC * ND];
__device__ float g_p[2][(size_t)NE * NC * ND];

// ---- smem geometry (words) ----
#define AST 36                    // A row stride: 32 k + 4 pad  -> frag banks 4r+tg unique
#define BST 136                   // B row stride: 128 n + 8 pad -> frag banks 8tg+g unique
#define A_STAGE_W (64 * AST)      // 2304 words
#define B_STAGE_W (32 * BST)      // 4352 words
#define STAGE_W   (A_STAGE_W + B_STAGE_W)   // 6656 words = 26624 B
#define NSTAGE 2                  // 2 stages -> 53KB -> 3 CTAs/SM

__device__ __forceinline__ uint32_t smem_u32(const void* p) {
    uint32_t a;
    asm("{ .reg .u64 t; cvta.to.shared.u64 t, %1; cvt.u32.u64 %0, t; }" : "=r"(a) : "l"(p));
    return a;
}
__device__ __forceinline__ uint32_t to_tf32u(float x) {
    uint32_t y; asm("cvt.rna.tf32.f32 %0, %1;" : "=r"(y) : "f"(x)); return y;
}
__device__ __forceinline__ float tanh_fast(float x) {
    float y; asm("tanh.approx.f32 %0, %1;" : "=f"(y) : "f"(x)); return y;
}
__device__ __forceinline__ float gelu_tanh(float v) {
    const float c0 = 0.7978845608028654f;
    const float c1 = 0.044715f;
    float u = c0 * fmaf(c1 * v * v, v, v);
    return 0.5f * v * (1.0f + tanh_fast(u));
}
__device__ __forceinline__ void cp16(uint32_t dst, const void* src) {
    asm volatile("cp.async.cg.shared.global [%0], [%1], 16;" :: "r"(dst), "l"(src));
}
#define CP_COMMIT() asm volatile("cp.async.commit_group;" ::: "memory")
#define CP_WAIT1()  asm volatile("cp.async.wait_group 1;"  ::: "memory")

// m16n8k8 tf32 MMA (full-rate atom, plain sm_80+ PTX)
__device__ __forceinline__ void mma8(float (&c)[4],
                                     uint32_t a0, uint32_t a1, uint32_t a2, uint32_t a3,
                                     uint32_t b0, uint32_t b1) {
    asm volatile("mma.sync.aligned.m16n8k8.row.col.f32.tf32.tf32.f32 "
                 "{%0,%1,%2,%3}, {%4,%5,%6,%7}, {%8,%9}, {%0,%1,%2,%3};"
                 : "+f"(c[0]), "+f"(c[1]), "+f"(c[2]), "+f"(c[3])
                 : "r"(a0), "r"(a1), "r"(a2), "r"(a3), "r"(b0), "r"(b1));
}

// MODE 0: C = tf32round(gelu(A@B + bias))      (GEMM1 -> g_h, A pre-rounded)
// MODE 1: C = A@B partial (no bias/act)        (GEMM2 K-split halves -> g_p)
// A is ALWAYS pre-rounded tf32 (no consumer cvt); B converted at consume.
template <int MODE, int KSTRIDE, int KLEN, int N>
__global__ __launch_bounds__(256, 3)
void moe_tf32(const float* __restrict__ A_all, const float* __restrict__ B_all,
              const float* __restrict__ bias_all, float* __restrict__ C_all)
{
    constexpr int NS = KLEN / 32;
    extern __shared__ float sm[];
    const uint32_t smb = smem_u32(sm);

    const int tid  = threadIdx.x;
    const int lane = tid & 31;
    const int wid  = tid >> 5;
    const int e    = blockIdx.y;
    const int n0   = blockIdx.x * 128;
    const int kb   = blockIdx.z * KLEN;

    const float* Ae = A_all    + (size_t)e * NC * KSTRIDE + kb;
    const float* Bg = B_all    + (size_t)e * KSTRIDE * N + (size_t)kb * N + n0;
    const float* be = bias_all + (size_t)e * N + n0;
    float*       Ce = C_all    + (MODE == 1 ? (size_t)blockIdx.z * NE * NC * N : 0)
                               + (size_t)e * NC * N + n0;

    const int wm = wid & 1, wn = wid >> 1;     // warp grid 2(M) x 4(N)
    const int g  = lane >> 2, tg = lane & 3;

    float acc[2][4][4];
    #pragma unroll
    for (int i = 0; i < 2; i++)
        #pragma unroll
        for (int j = 0; j < 4; j++)
            #pragma unroll
            for (int k = 0; k < 4; k++) acc[i][j][k] = 0.0f;

    // ---- async stage fill: A[64x32] row-major, B[32x128] k-major rows ----
    auto ISSUE = [&](int s) {
        const int buf = s & 1;
        const uint32_t sA = smb + (uint32_t)(buf * STAGE_W) * 4u;
        const uint32_t sB = sA + A_STAGE_W * 4u;
        const int k0 = s * 32;
        #pragma unroll
        for (int r = 0; r < 2; r++) {              // A: 512 x 16B
            int idx = r * 256 + tid;
            int row = idx >> 3, c = idx & 7;
            cp16(sA + (uint32_t)(row * AST + c * 4) * 4u,
                 Ae + (size_t)row * KSTRIDE + k0 + c * 4);
        }
        #pragma unroll
        for (int r = 0; r < 4; r++) {              // B: 1024 x 16B
            int idx = r * 256 + tid;
            int row = idx >> 5, c = idx & 31;
            cp16(sB + (uint32_t)(row * BST + c * 4) * 4u,
                 Bg + (size_t)(k0 + row) * N + c * 4);
        }
    };

    // ---- consume one stage (A raw bits, B cvt) ----
    auto COMPUTE = [&](int buf) {
        const float* sAf = sm + buf * STAGE_W;
        const float* sBf = sAf + A_STAGE_W;
        #pragma unroll
        for (int h = 0; h < 4; h++) {              // four k8 steps
            uint32_t A0[2], A1[2], A2[2], A3[2];
            #pragma unroll
            for (int ma = 0; ma < 2; ma++) {
                const float* p = sAf + (wm * 32 + ma * 16 + g) * AST + h * 8 + tg;
                A0[ma] = __float_as_uint(p[0]);
                A2[ma] = __float_as_uint(p[4]);
                A1[ma] = __float_as_uint(p[8 * AST]);
                A3[ma] = __float_as_uint(p[8 * AST + 4]);
            }
            #pragma unroll
            for (int na = 0; na < 4; na++) {
                const float* q = sBf + (h * 8 + tg) * BST + wn * 32 + na * 8 + g;
                uint32_t B0 = to_tf32u(q[0]);
                uint32_t B1 = to_tf32u(q[4 * BST]);
                mma8(acc[0][na], A0[0], A1[0], A2[0], A3[0], B0, B1);
                mma8(acc[1][na], A0[1], A1[1], A2[1], A3[1], B0, B1);
            }
        }
    };

    // ---- 2-stage pipeline ----
    ISSUE(0); CP_COMMIT();
    ISSUE(1); CP_COMMIT();
    for (int s = 0; s < NS; s++) {
        CP_WAIT1();                 // stage s resident (newest in-flight = s+1)
        __syncthreads();
        COMPUTE(s & 1);
        __syncthreads();            // all readers done before overwrite
        if (s + 2 < NS) ISSUE(s + 2);
        CP_COMMIT();                // keep group count uniform (may be empty)
    }

    // ---- epilogue ----
    if (MODE == 0) {
        float2 bvv[4];
        #pragma unroll
        for (int na = 0; na < 4; na++)
            bvv[na] = *reinterpret_cast<const float2*>(be + wn * 32 + na * 8 + 2 * tg);
        #pragma unroll
        for (int ma = 0; ma < 2; ma++) {
            int row0 = wm * 32 + ma * 16 + g;
            #pragma unroll
            for (int na = 0; na < 4; na++) {
                int col = wn * 32 + na * 8 + 2 * tg;
                float v0 = gelu_tanh(acc[ma][na][0] + bvv[na].x);
                float v1 = gelu_tanh(acc[ma][na][1] + bvv[na].y);
                float v2 = gelu_tanh(acc[ma][na][2] + bvv[na].x);
                float v3 = gelu_tanh(acc[ma][na][3] + bvv[na].y);
                // store tf32-rounded so GEMM2 consumes A without cvt
                float2 w0 = make_float2(__uint_as_float(to_tf32u(v0)),
                                        __uint_as_float(to_tf32u(v1)));
                float2 w1 = make_float2(__uint_as_float(to_tf32u(v2)),
                                        __uint_as_float(to_tf32u(v3)));
                *reinterpret_cast<float2*>(Ce + (size_t)row0 * N + col)       = w0;
                *reinterpret_cast<float2*>(Ce + (size_t)(row0 + 8) * N + col) = w1;
            }
        }
    } else {
        #pragma unroll
        for (int ma = 0; ma < 2; ma++) {
            int row0 = wm * 32 + ma * 16 + g;
            #pragma unroll
            for (int na = 0; na < 4; na++) {
                int col = wn * 32 + na * 8 + 2 * tg;
                *reinterpret_cast<float2*>(Ce + (size_t)row0 * N + col) =
                    make_float2(acc[ma][na][0], acc[ma][na][1]);
                *reinterpret_cast<float2*>(Ce + (size_t)(row0 + 8) * N + col) =
                    make_float2(acc[ma][na][2], acc[ma][na][3]);
            }
        }
    }
}

// round x -> tf32 once (removes all A-side cvt in GEMM1)
__global__ void round_x(const float* __restrict__ x, float* __restrict__ xo) {
    int i = blockIdx.x * blockDim.x + threadIdx.x;      // float4 index
    float4 v = reinterpret_cast<const float4*>(x)[i];
    v.x = __uint_as_float(to_tf32u(v.x));
    v.y = __uint_as_float(to_tf32u(v.y));
    v.z = __uint_as_float(to_tf32u(v.z));
    v.w = __uint_as_float(to_tf32u(v.w));
    reinterpret_cast<float4*>(xo)[i] = v;
}

// out = p0 + p1 + bias   (deterministic fixed-order reduction)
__global__ void fixup2(const float* __restrict__ p0, const float* __restrict__ p1,
                       const float* __restrict__ b2, float* __restrict__ out) {
    int i = blockIdx.x * blockDim.x + threadIdx.x;      // float4 index
    int i4 = i * 4;
    int e   = i4 >> 16;                                  // / (64*1024)
    int col = i4 & (ND - 1);
    float4 a = reinterpret_cast<const float4*>(p0)[i];
    float4 b = reinterpret_cast<const float4*>(p1)[i];
    float4 c = *reinterpret_cast<const float4*>(b2 + (size_t)e * ND + col);
    reinterpret_cast<float4*>(out)[i] =
        make_float4(a.x + b.x + c.x, a.y + b.y + c.y,
                    a.z + b.z + c.z, a.w + b.w + c.w);
}

// ---------------- host launch ----------------
extern "C" void kernel_launch(void* const* d_in, const int* in_sizes, int n_in,
                              void* d_out, int out_size)
{
    (void)in_sizes; (void)n_in; (void)out_size;
    const float* x  = (const float*)d_in[0];   // [1, E*C, D]
    const float* W1 = (const float*)d_in[1];   // [E, D, F]
    const float* b1 = (const float*)d_in[2];   // [E, F]
    const float* W2 = (const float*)d_in[3];   // [E, F, D]
    const float* b2 = (const float*)d_in[4];   // [E, D]
    float* out = (float*)d_out;                // [1, E*C, D]

    float *hbuf = nullptr, *xbuf = nullptr, *pbuf = nullptr;
    cudaGetSymbolAddress((void**)&hbuf, g_h);
    cudaGetSymbolAddress((void**)&xbuf, g_x);
    cudaGetSymbolAddress((void**)&pbuf, g_p);

    const int smem = NSTAGE * STAGE_W * (int)sizeof(float);   // 53248 B

    cudaFuncSetAttribute((const void*)moe_tf32<0, ND, ND, NF>,
                         cudaFuncAttributeMaxDynamicSharedMemorySize, smem);
    cudaFuncSetAttribute((const void*)moe_tf32<1, NF, KSPLIT2, ND>,
                         cudaFuncAttributeMaxDynamicSharedMemorySize, smem);

    const int nelem4 = NE * NC * ND / 4;       // 524288 float4s

    // 0) pre-round x to tf32
    round_x<<<nelem4 / 256, 256>>>(x, xbuf);
    // 1) h = tf32(gelu(x @ W1 + b1))   [E,64,1024] x [E,1024,4096]
    moe_tf32<0, ND, ND, NF><<<dim3(NF / 128, NE, 1), 256, smem>>>(xbuf, W1, b1, hbuf);
    // 2) partials: p[z] = h @ W2[z-half]   (K split 2 x 2048)
    moe_tf32<1, NF, KSPLIT2, ND><<<dim3(ND / 128, NE, 2), 256, smem>>>(hbuf, W2, b2, pbuf);
    // 3) out = p0 + p1 + b2
    fixup2<<<nelem4 / 256, 256>>>(pbuf, pbuf + (size_t)NE * NC * ND, b2, out);
}

// round 7
// speedup vs baseline: 5.3329x; 1.0573x over previous
#include <cuda_runtime.h>
#include <cstdint>

#define NE 32     // experts
#define NC 64     // rows per expert
#define ND 1024   // d_model
#define NF 4096   // d_ff
#define KSPLIT2 2048              // GEMM2 K-split length

// static scratch (no allocation): h (32MB), rounded x (8MB), GEMM2 partials (16MB)
__device__ float g_h[(size_t)NE * NC * NF];
__device__ float g_x[(size_t)NE * NC * ND];
__device__ float g_p[2][(size_t)NE * NC * ND];

// ---- GEMM1 smem geometry (words): tile 64x128, BK=32, 3 stages ----
#define AST 36
#define BST1 136
#define A_W  (64 * AST)                    // 2304
#define B1_W (32 * BST1)                   // 4352
#define STG1_W (A_W + B1_W)                // 6656 (26624 B); x3 = 79872 B
// ---- GEMM2 smem geometry (words): tile 64x256, BK=32, 2 stages ----
#define BST2 264
#define B2_W (32 * BST2)                   // 8448
#define STG2_W (A_W + B2_W)                // 10752 (43008 B); x2 = 86016 B

__device__ __forceinline__ uint32_t smem_u32(const void* p) {
    uint32_t a;
    asm("{ .reg .u64 t; cvta.to.shared.u64 t, %1; cvt.u32.u64 %0, t; }" : "=r"(a) : "l"(p));
    return a;
}
__device__ __forceinline__ uint32_t to_tf32u(float x) {
    uint32_t y; asm("cvt.rna.tf32.f32 %0, %1;" : "=r"(y) : "f"(x)); return y;
}
__device__ __forceinline__ float tanh_fast(float x) {
    float y; asm("tanh.approx.f32 %0, %1;" : "=f"(y) : "f"(x)); return y;
}
__device__ __forceinline__ float gelu_tanh(float v) {
    const float c0 = 0.7978845608028654f;
    const float c1 = 0.044715f;
    float u = c0 * fmaf(c1 * v * v, v, v);
    return 0.5f * v * (1.0f + tanh_fast(u));
}
__device__ __forceinline__ void cp16(uint32_t dst, const void* src) {
    asm volatile("cp.async.cg.shared.global [%0], [%1], 16;" :: "r"(dst), "l"(src));
}
#define CP_COMMIT() asm volatile("cp.async.commit_group;" ::: "memory")
#define CP_WAIT1()  asm volatile("cp.async.wait_group 1;"  ::: "memory")

__device__ __forceinline__ void mma8(float (&c)[4],
                                     uint32_t a0, uint32_t a1, uint32_t a2, uint32_t a3,
                                     uint32_t b0, uint32_t b1) {
    asm volatile("mma.sync.aligned.m16n8k8.row.col.f32.tf32.tf32.f32 "
                 "{%0,%1,%2,%3}, {%4,%5,%6,%7}, {%8,%9}, {%0,%1,%2,%3};"
                 : "+f"(c[0]), "+f"(c[1]), "+f"(c[2]), "+f"(c[3])
                 : "r"(a0), "r"(a1), "r"(a2), "r"(a3), "r"(b0), "r"(b1));
}

// ============ GEMM1: h = tf32(gelu(A@B + b)), tile 64x128, 3-stage ============
// A pre-rounded tf32 (raw-bit fragments); B cvt at consume.
template <int K, int N>
__global__ __launch_bounds__(256, 2)
void moe_g1(const float* __restrict__ A_all, const float* __restrict__ B_all,
            const float* __restrict__ bias_all, float* __restrict__ C_all)
{
    constexpr int NS = K / 32;
    extern __shared__ float sm[];
    const uint32_t smb = smem_u32(sm);

    const int tid  = threadIdx.x;
    const int lane = tid & 31;
    const int wid  = tid >> 5;
    const int e    = blockIdx.y;
    const int n0   = blockIdx.x * 128;

    const float* Ae = A_all    + (size_t)e * NC * K;
    const float* Bg = B_all    + (size_t)e * K * N + n0;
    const float* be = bias_all + (size_t)e * N + n0;
    float*       Ce = C_all    + (size_t)e * NC * N + n0;

    const int wm = wid & 1, wn = wid >> 1;     // 2(M) x 4(N), warp tile 32x32
    const int g  = lane >> 2, tg = lane & 3;

    float acc[2][4][4];
    #pragma unroll
    for (int i = 0; i < 2; i++)
        #pragma unroll
        for (int j = 0; j < 4; j++)
            #pragma unroll
            for (int k = 0; k < 4; k++) acc[i][j][k] = 0.0f;

    auto ISSUE = [&](int s) {
        const int buf = s % 3;
        const uint32_t sA = smb + (uint32_t)(buf * STG1_W) * 4u;
        const uint32_t sB = sA + A_W * 4u;
        const int k0 = s * 32;
        #pragma unroll
        for (int r = 0; r < 2; r++) {
            int idx = r * 256 + tid;
            int row = idx >> 3, c = idx & 7;
            cp16(sA + (uint32_t)(row * AST + c * 4) * 4u,
                 Ae + (size_t)row * K + k0 + c * 4);
        }
        #pragma unroll
        for (int r = 0; r < 4; r++) {
            int idx = r * 256 + tid;
            int row = idx >> 5, c = idx & 31;
            cp16(sB + (uint32_t)(row * BST1 + c * 4) * 4u,
                 Bg + (size_t)(k0 + row) * N + c * 4);
        }
    };

    auto COMPUTE = [&](int buf) {
        const float* sAf = sm + buf * STG1_W;
        const float* sBf = sAf + A_W;
        #pragma unroll
        for (int h = 0; h < 4; h++) {
            uint32_t A0[2], A1[2], A2[2], A3[2];
            #pragma unroll
            for (int ma = 0; ma < 2; ma++) {
                const float* p = sAf + (wm * 32 + ma * 16 + g) * AST + h * 8 + tg;
                A0[ma] = __float_as_uint(p[0]);
                A2[ma] = __float_as_uint(p[4]);
                A1[ma] = __float_as_uint(p[8 * AST]);
                A3[ma] = __float_as_uint(p[8 * AST + 4]);
            }
            #pragma unroll
            for (int na = 0; na < 4; na++) {
                const float* q = sBf + (h * 8 + tg) * BST1 + wn * 32 + na * 8 + g;
                uint32_t B0 = to_tf32u(q[0]);
                uint32_t B1 = to_tf32u(q[4 * BST1]);
                mma8(acc[0][na], A0[0], A1[0], A2[0], A3[0], B0, B1);
                mma8(acc[1][na], A0[1], A1[1], A2[1], A3[1], B0, B1);
            }
        }
    };

    // 3-stage, single sync per slab
    ISSUE(0); CP_COMMIT();
    ISSUE(1); CP_COMMIT();
    CP_WAIT1();
    __syncthreads();
    for (int s = 0; s < NS; s++) {
        if (s + 2 < NS) ISSUE(s + 2);
        CP_COMMIT();
        COMPUTE(s % 3);
        CP_WAIT1();
        __syncthreads();
    }

    // epilogue: bias + gelu + tf32 round (h consumed raw by GEMM2)
    float2 bvv[4];
    #pragma unroll
    for (int na = 0; na < 4; na++)
        bvv[na] = *reinterpret_cast<const float2*>(be + wn * 32 + na * 8 + 2 * tg);
    #pragma unroll
    for (int ma = 0; ma < 2; ma++) {
        int row0 = wm * 32 + ma * 16 + g;
        #pragma unroll
        for (int na = 0; na < 4; na++) {
            int col = wn * 32 + na * 8 + 2 * tg;
            float v0 = gelu_tanh(acc[ma][na][0] + bvv[na].x);
            float v1 = gelu_tanh(acc[ma][na][1] + bvv[na].y);
            float v2 = gelu_tanh(acc[ma][na][2] + bvv[na].x);
            float v3 = gelu_tanh(acc[ma][na][3] + bvv[na].y);
            float2 w0 = make_float2(__uint_as_float(to_tf32u(v0)),
                                    __uint_as_float(to_tf32u(v1)));
            float2 w1 = make_float2(__uint_as_float(to_tf32u(v2)),
                                    __uint_as_float(to_tf32u(v3)));
            *reinterpret_cast<float2*>(Ce + (size_t)row0 * N + col)       = w0;
            *reinterpret_cast<float2*>(Ce + (size_t)(row0 + 8) * N + col) = w1;
        }
    }
}

// ====== GEMM2: partials p[z] = A@B, tile 64x256, warp tile 32x64, 2-stage ======
// A (= h) pre-rounded tf32; B cvt at consume. K split via blockIdx.z.
template <int KSTRIDE, int KLEN, int N>
__global__ __launch_bounds__(256, 2)
void moe_g2(const float* __restrict__ A_all, const float* __restrict__ B_all,
            float* __restrict__ C_all)
{
    constexpr int NS = KLEN / 32;
    extern __shared__ float sm[];
    const uint32_t smb = smem_u32(sm);

    const int tid  = threadIdx.x;
    const int lane = tid & 31;
    const int wid  = tid >> 5;
    const int e    = blockIdx.y;
    const int n0   = blockIdx.x * 256;
    const int kb   = blockIdx.z * KLEN;

    const float* Ae = A_all + (size_t)e * NC * KSTRIDE + kb;
    const float* Bg = B_all + (size_t)e * KSTRIDE * N + (size_t)kb * N + n0;
    float*       Ce = C_all + (size_t)blockIdx.z * NE * NC * N
                            + (size_t)e * NC * N + n0;

    const int wm = wid & 1, wn = wid >> 1;     // 2(M) x 4(N), warp tile 32x64
    const int g  = lane >> 2, tg = lane & 3;

    float acc[2][8][4];
    #pragma unroll
    for (int i = 0; i < 2; i++)
        #pragma unroll
        for (int j = 0; j < 8; j++)
            #pragma unroll
            for (int k = 0; k < 4; k++) acc[i][j][k] = 0.0f;

    auto ISSUE = [&](int s) {
        const int buf = s & 1;
        const uint32_t sA = smb + (uint32_t)(buf * STG2_W) * 4u;
        const uint32_t sB = sA + A_W * 4u;
        const int k0 = s * 32;
        #pragma unroll
        for (int r = 0; r < 2; r++) {              // A: 512 x 16B
            int idx = r * 256 + tid;
            int row = idx >> 3, c = idx & 7;
            cp16(sA + (uint32_t)(row * AST + c * 4) * 4u,
                 Ae + (size_t)row * KSTRIDE + k0 + c * 4);
        }
        #pragma unroll
        for (int r = 0; r < 8; r++) {              // B: 2048 x 16B (32 rows x 256)
            int idx = r * 256 + tid;
            int row = idx >> 6, c = idx & 63;
            cp16(sB + (uint32_t)(row * BST2 + c * 4) * 4u,
                 Bg + (size_t)(k0 + row) * N + c * 4);
        }
    };

    auto COMPUTE = [&](int buf) {
        const float* sAf = sm + buf * STG2_W;
        const float* sBf = sAf + A_W;
        #pragma unroll
        for (int h = 0; h < 4; h++) {
            uint32_t A0[2], A1[2], A2[2], A3[2];
            #pragma unroll
            for (int ma = 0; ma < 2; ma++) {
                const float* p = sAf + (wm * 32 + ma * 16 + g) * AST + h * 8 + tg;
                A0[ma] = __float_as_uint(p[0]);
                A2[ma] = __float_as_uint(p[4]);
                A1[ma] = __float_as_uint(p[8 * AST]);
                A3[ma] = __float_as_uint(p[8 * AST + 4]);
            }
            #pragma unroll
            for (int na = 0; na < 8; na++) {       // bank = 8*tg + g -> conflict-free
                const float* q = sBf + (h * 8 + tg) * BST2 + wn * 64 + na * 8 + g;
                uint32_t B0 = to_tf32u(q[0]);
                uint32_t B1 = to_tf32u(q[4 * BST2]);
                mma8(acc[0][na], A0[0], A1[0], A2[0], A3[0], B0, B1);
                mma8(acc[1][na], A0[1], A1[1], A2[1], A3[1], B0, B1);
            }
        }
    };

    // 2-stage pipeline
    ISSUE(0); CP_COMMIT();
    ISSUE(1); CP_COMMIT();
    for (int s = 0; s < NS; s++) {
        CP_WAIT1();
        __syncthreads();
        COMPUTE(s & 1);
        __syncthreads();
        if (s + 2 < NS) ISSUE(s + 2);
        CP_COMMIT();
    }

    // epilogue: raw partial stores
    #pragma unroll
    for (int ma = 0; ma < 2; ma++) {
        int row0 = wm * 32 + ma * 16 + g;
        #pragma unroll
        for (int na = 0; na < 8; na++) {
            int col = wn * 64 + na * 8 + 2 * tg;
            *reinterpret_cast<float2*>(Ce + (size_t)row0 * N + col) =
                make_float2(acc[ma][na][0], acc[ma][na][1]);
            *reinterpret_cast<float2*>(Ce + (size_t)(row0 + 8) * N + col) =
                make_float2(acc[ma][na][2], acc[ma][na][3]);
        }
    }
}

// round x -> tf32 once
__global__ void round_x(const float* __restrict__ x, float* __restrict__ xo) {
    int i = blockIdx.x * blockDim.x + threadIdx.x;
    float4 v = reinterpret_cast<const float4*>(x)[i];
    v.x = __uint_as_float(to_tf32u(v.x));
    v.y = __uint_as_float(to_tf32u(v.y));
    v.z = __uint_as_float(to_tf32u(v.z));
    v.w = __uint_as_float(to_tf32u(v.w));
    reinterpret_cast<float4*>(xo)[i] = v;
}

// out = p0 + p1 + bias (deterministic)
__global__ void fixup2(const float* __restrict__ p0, const float* __restrict__ p1,
                       const float* __restrict__ b2, float* __restrict__ out) {
    int i = blockIdx.x * blockDim.x + threadIdx.x;
    int i4 = i * 4;
    int e   = i4 >> 16;
    int col = i4 & (ND - 1);
    float4 a = reinterpret_cast<const float4*>(p0)[i];
    float4 b = reinterpret_cast<const float4*>(p1)[i];
    float4 c = *reinterpret_cast<const float4*>(b2 + (size_t)e * ND + col);
    reinterpret_cast<float4*>(out)[i] =
        make_float4(a.x + b.x + c.x, a.y + b.y + c.y,
                    a.z + b.z + c.z, a.w + b.w + c.w);
}

// ---------------- host launch ----------------
extern "C" void kernel_launch(void* const* d_in, const int* in_sizes, int n_in,
                              void* d_out, int out_size)
{
    (void)in_sizes; (void)n_in; (void)out_size;
    const float* x  = (const float*)d_in[0];
    const float* W1 = (const float*)d_in[1];
    const float* b1 = (const float*)d_in[2];
    const float* W2 = (const float*)d_in[3];
    const float* b2 = (const float*)d_in[4];
    float* out = (float*)d_out;

    float *hbuf = nullptr, *xbuf = nullptr, *pbuf = nullptr;
    cudaGetSymbolAddress((void**)&hbuf, g_h);
    cudaGetSymbolAddress((void**)&xbuf, g_x);
    cudaGetSymbolAddress((void**)&pbuf, g_p);

    const int smem1 = 3 * STG1_W * (int)sizeof(float);   // 79872 B
    const int smem2 = 2 * STG2_W * (int)sizeof(float);   // 86016 B

    cudaFuncSetAttribute((const void*)moe_g1<ND, NF>,
                         cudaFuncAttributeMaxDynamicSharedMemorySize, smem1);
    cudaFuncSetAttribute((const void*)moe_g2<NF, KSPLIT2, ND>,
                         cudaFuncAttributeMaxDynamicSharedMemorySize, smem2);

    const int nelem4 = NE * NC * ND / 4;

    // 0) pre-round x
    round_x<<<nelem4 / 256, 256>>>(x, xbuf);
    // 1) h = tf32(gelu(x @ W1 + b1))
    moe_g1<ND, NF><<<dim3(NF / 128, NE, 1), 256, smem1>>>(xbuf, W1, b1, hbuf);
    // 2) partials: p[z] = h @ W2[z-half]
    moe_g2<NF, KSPLIT2, ND><<<dim3(ND / 256, NE, 2), 256, smem2>>>(hbuf, W2, pbuf);
    // 3) out = p0 + p1 + b2
    fixup2<<<nelem4 / 256, 256>>>(pbuf, pbuf + (size_t)NE * NC * ND, b2, out);
}

// round 8
// speedup vs baseline: 5.6845x; 1.0659x over previous
#include <cuda_runtime.h>
#include <cstdint>

#define NE 32     // experts
#define NC 64     // rows per expert
#define ND 1024   // d_model
#define NF 4096   // d_ff
#define KSPLIT2 2048              // GEMM2 K-split length

// static scratch (no allocation): h (32MB), rounded x (8MB), GEMM2 partials (16MB)
__device__ float g_h[(size_t)NE * NC * NF];
__device__ float g_x[(size_t)NE * NC * ND];
__device__ float g_p[2][(size_t)NE * NC * ND];

// ---- smem geometry (words): CTA tile 64x256, BK=32, 2 stages ----
#define AST 36                    // A row stride (32 k + 4 pad): frag bank = 4g+tg
#define BST 264                   // B row stride (256 n + 8 pad): frag bank = 8tg+g
#define A_W  (64 * AST)           // 2304 words
#define B_W  (32 * BST)           // 8448 words
#define STG_W (A_W + B_W)         // 10752 words = 43008 B; x2 = 86016 B -> 2 CTAs/SM

__device__ __forceinline__ uint32_t smem_u32(const void* p) {
    uint32_t a;
    asm("{ .reg .u64 t; cvta.to.shared.u64 t, %1; cvt.u32.u64 %0, t; }" : "=r"(a) : "l"(p));
    return a;
}
__device__ __forceinline__ uint32_t to_tf32u(float x) {
    uint32_t y; asm("cvt.rna.tf32.f32 %0, %1;" : "=r"(y) : "f"(x)); return y;
}
__device__ __forceinline__ float tanh_fast(float x) {
    float y; asm("tanh.approx.f32 %0, %1;" : "=f"(y) : "f"(x)); return y;
}
__device__ __forceinline__ float gelu_tanh(float v) {
    const float c0 = 0.7978845608028654f;
    const float c1 = 0.044715f;
    float u = c0 * fmaf(c1 * v * v, v, v);
    return 0.5f * v * (1.0f + tanh_fast(u));
}
__device__ __forceinline__ void cp16(uint32_t dst, const void* src) {
    asm volatile("cp.async.cg.shared.global [%0], [%1], 16;" :: "r"(dst), "l"(src));
}
#define CP_COMMIT() asm volatile("cp.async.commit_group;" ::: "memory")
#define CP_WAIT1()  asm volatile("cp.async.wait_group 1;"  ::: "memory")

__device__ __forceinline__ void mma8(float (&c)[4],
                                     uint32_t a0, uint32_t a1, uint32_t a2, uint32_t a3,
                                     uint32_t b0, uint32_t b1) {
    asm volatile("mma.sync.aligned.m16n8k8.row.col.f32.tf32.tf32.f32 "
                 "{%0,%1,%2,%3}, {%4,%5,%6,%7}, {%8,%9}, {%0,%1,%2,%3};"
                 : "+f"(c[0]), "+f"(c[1]), "+f"(c[2]), "+f"(c[3])
                 : "r"(a0), "r"(a1), "r"(a2), "r"(a3), "r"(b0), "r"(b1));
}

// Unified grouped-GEMM: CTA tile 64x256, 4 warps, warp tile 64x64.
// MODE 0: C = tf32round(gelu(A@B + bias))   (GEMM1 -> g_h)
// MODE 1: C = A@B partial (K-split via blockIdx.z, no bias)  (GEMM2 -> g_p)
// A is pre-rounded tf32 (raw-bit fragments); B cvt at consume.
template <int MODE, int KSTRIDE, int KLEN, int N>
__global__ __launch_bounds__(128, 2)
void moe_wg(const float* __restrict__ A_all, const float* __restrict__ B_all,
            const float* __restrict__ bias_all, float* __restrict__ C_all)
{
    constexpr int NS = KLEN / 32;
    extern __shared__ float sm[];
    const uint32_t smb = smem_u32(sm);

    const int tid  = threadIdx.x;
    const int lane = tid & 31;
    const int wid  = tid >> 5;                 // 0..3 = n-block
    const int e    = blockIdx.y;
    const int n0   = blockIdx.x * 256;
    const int kb   = (MODE == 1 ? blockIdx.z * KLEN : 0);

    const float* Ae = A_all    + (size_t)e * NC * KSTRIDE + kb;
    const float* Bg = B_all    + (size_t)e * KSTRIDE * N + (size_t)kb * N + n0;
    const float* be = bias_all + (size_t)e * N + n0;
    float*       Ce = C_all    + (MODE == 1 ? (size_t)blockIdx.z * NE * NC * N : 0)
                               + (size_t)e * NC * N + n0;

    const int g  = lane >> 2, tg = lane & 3;

    float acc[4][8][4];                         // [ma][na][c] = 128 regs
    #pragma unroll
    for (int i = 0; i < 4; i++)
        #pragma unroll
        for (int j = 0; j < 8; j++)
            #pragma unroll
            for (int k = 0; k < 4; k++) acc[i][j][k] = 0.0f;

    // ---- async stage fill (128 threads): A 512 x 16B, B 2048 x 16B ----
    auto ISSUE = [&](int s) {
        const int buf = s & 1;
        const uint32_t sA = smb + (uint32_t)(buf * STG_W) * 4u;
        const uint32_t sB = sA + A_W * 4u;
        const int k0 = s * 32;
        #pragma unroll
        for (int r = 0; r < 4; r++) {
            int idx = r * 128 + tid;
            int row = idx >> 3, c = idx & 7;
            cp16(sA + (uint32_t)(row * AST + c * 4) * 4u,
                 Ae + (size_t)row * KSTRIDE + k0 + c * 4);
        }
        #pragma unroll
        for (int r = 0; r < 16; r++) {
            int idx = r * 128 + tid;
            int row = idx >> 6, c = idx & 63;
            cp16(sB + (uint32_t)(row * BST + c * 4) * 4u,
                 Bg + (size_t)(k0 + row) * N + c * 4);
        }
    };

    // ---- consume one stage: warp tile 64x64 (4 ma x 8 na) ----
    auto COMPUTE = [&](int buf) {
        const float* sAf = sm + buf * STG_W;
        const float* sBf = sAf + A_W;
        #pragma unroll
        for (int h = 0; h < 4; h++) {           // four k8 steps
            uint32_t A0[4], A1[4], A2[4], A3[4];
            #pragma unroll
            for (int ma = 0; ma < 4; ma++) {
                const float* p = sAf + (ma * 16 + g) * AST + h * 8 + tg;
                A0[ma] = __float_as_uint(p[0]);
                A2[ma] = __float_as_uint(p[4]);
                A1[ma] = __float_as_uint(p[8 * AST]);
                A3[ma] = __float_as_uint(p[8 * AST + 4]);
            }
            #pragma unroll
            for (int na = 0; na < 8; na++) {
                const float* q = sBf + (h * 8 + tg) * BST + wid * 64 + na * 8 + g;
                uint32_t B0 = to_tf32u(q[0]);
                uint32_t B1 = to_tf32u(q[4 * BST]);
                #pragma unroll
                for (int ma = 0; ma < 4; ma++)
                    mma8(acc[ma][na], A0[ma], A1[ma], A2[ma], A3[ma], B0, B1);
            }
        }
    };

    // ---- 2-stage pipeline ----
    ISSUE(0); CP_COMMIT();
    ISSUE(1); CP_COMMIT();
    for (int s = 0; s < NS; s++) {
        CP_WAIT1();
        __syncthreads();
        COMPUTE(s & 1);
        __syncthreads();
        if (s + 2 < NS) ISSUE(s + 2);
        CP_COMMIT();
    }

    // ---- epilogue ----
    if (MODE == 0) {
        float2 bvv[8];
        #pragma unroll
        for (int na = 0; na < 8; na++)
            bvv[na] = *reinterpret_cast<const float2*>(be + wid * 64 + na * 8 + 2 * tg);
        #pragma unroll
        for (int ma = 0; ma < 4; ma++) {
            int row0 = ma * 16 + g;
            #pragma unroll
            for (int na = 0; na < 8; na++) {
                int col = wid * 64 + na * 8 + 2 * tg;
                float v0 = gelu_tanh(acc[ma][na][0] + bvv[na].x);
                float v1 = gelu_tanh(acc[ma][na][1] + bvv[na].y);
                float v2 = gelu_tanh(acc[ma][na][2] + bvv[na].x);
                float v3 = gelu_tanh(acc[ma][na][3] + bvv[na].y);
                float2 w0 = make_float2(__uint_as_float(to_tf32u(v0)),
                                        __uint_as_float(to_tf32u(v1)));
                float2 w1 = make_float2(__uint_as_float(to_tf32u(v2)),
                                        __uint_as_float(to_tf32u(v3)));
                *reinterpret_cast<float2*>(Ce + (size_t)row0 * N + col)       = w0;
                *reinterpret_cast<float2*>(Ce + (size_t)(row0 + 8) * N + col) = w1;
            }
        }
    } else {
        #pragma unroll
        for (int ma = 0; ma < 4; ma++) {
            int row0 = ma * 16 + g;
            #pragma unroll
            for (int na = 0; na < 8; na++) {
                int col = wid * 64 + na * 8 + 2 * tg;
                *reinterpret_cast<float2*>(Ce + (size_t)row0 * N + col) =
                    make_float2(acc[ma][na][0], acc[ma][na][1]);
                *reinterpret_cast<float2*>(Ce + (size_t)(row0 + 8) * N + col) =
                    make_float2(acc[ma][na][2], acc[ma][na][3]);
            }
        }
    }
}

// round x -> tf32 once
__global__ void round_x(const float* __restrict__ x, float* __restrict__ xo) {
    int i = blockIdx.x * blockDim.x + threadIdx.x;
    float4 v = reinterpret_cast<const float4*>(x)[i];
    v.x = __uint_as_float(to_tf32u(v.x));
    v.y = __uint_as_float(to_tf32u(v.y));
    v.z = __uint_as_float(to_tf32u(v.z));
    v.w = __uint_as_float(to_tf32u(v.w));
    reinterpret_cast<float4*>(xo)[i] = v;
}

// out = p0 + p1 + bias (deterministic fixed-order)
__global__ void fixup2(const float* __restrict__ p0, const float* __restrict__ p1,
                       const float* __restrict__ b2, float* __restrict__ out) {
    int i = blockIdx.x * blockDim.x + threadIdx.x;
    int i4 = i * 4;
    int e   = i4 >> 16;
    int col = i4 & (ND - 1);
    float4 a = reinterpret_cast<const float4*>(p0)[i];
    float4 b = reinterpret_cast<const float4*>(p1)[i];
    float4 c = *reinterpret_cast<const float4*>(b2 + (size_t)e * ND + col);
    reinterpret_cast<float4*>(out)[i] =
        make_float4(a.x + b.x + c.x, a.y + b.y + c.y,
                    a.z + b.z + c.z, a.w + b.w + c.w);
}

// ---------------- host launch ----------------
extern "C" void kernel_launch(void* const* d_in, const int* in_sizes, int n_in,
                              void* d_out, int out_size)
{
    (void)in_sizes; (void)n_in; (void)out_size;
    const float* x  = (const float*)d_in[0];
    const float* W1 = (const float*)d_in[1];
    const float* b1 = (const float*)d_in[2];
    const float* W2 = (const float*)d_in[3];
    const float* b2 = (const float*)d_in[4];
    float* out = (float*)d_out;

    float *hbuf = nullptr, *xbuf = nullptr, *pbuf = nullptr;
    cudaGetSymbolAddress((void**)&hbuf, g_h);
    cudaGetSymbolAddress((void**)&xbuf, g_x);
    cudaGetSymbolAddress((void**)&pbuf, g_p);

    const int smem = 2 * STG_W * (int)sizeof(float);   // 86016 B

    cudaFuncSetAttribute((const void*)moe_wg<0, ND, ND, NF>,
                         cudaFuncAttributeMaxDynamicSharedMemorySize, smem);
    cudaFuncSetAttribute((const void*)moe_wg<1, NF, KSPLIT2, ND>,
                         cudaFuncAttributeMaxDynamicSharedMemorySize, smem);

    const int nelem4 = NE * NC * ND / 4;

    // 0) pre-round x
    round_x<<<nelem4 / 256, 256>>>(x, xbuf);
    // 1) h = tf32(gelu(x @ W1 + b1))   [E,64,1024] x [E,1024,4096]
    moe_wg<0, ND, ND, NF><<<dim3(NF / 256, NE, 1), 128, smem>>>(xbuf, W1, b1, hbuf);
    // 2) partials: p[z] = h @ W2[z-half]  (K split 2 x 2048)
    moe_wg<1, NF, KSPLIT2, ND><<<dim3(ND / 256, NE, 2), 128, smem>>>(hbuf, W2, b2, pbuf);
    // 3) out = p0 + p1 + b2
    fixup2<<<nelem4 / 256, 256>>>(pbuf, pbuf + (size_t)NE * NC * ND, b2, out);
}